// round 8
// baseline (speedup 1.0000x reference)
#include <cuda_runtime.h>
#include <cuda_bf16.h>
#include <cstdint>

#define NN 25000
#define EE 400000
#define DD 256
#define FEAT 32
#define HOPS 4
#define SCAN_T 1024

// ---------------- device scratch (static, no allocation) ----------------
__device__ __align__(16) float  g_h  [(size_t)NN * DD];            // plain h (ping)
__device__ __align__(16) float  g_h2 [(size_t)NN * DD];            // plain h (pong)
__device__ __align__(16) float2 g_hs0[(size_t)NN * DD];            // split h (ping)
__device__ __align__(16) float2 g_hs1[(size_t)NN * DD];            // split h (pong)
__device__ __align__(16) float2 g_S2 [(size_t)NN * DD];            // split S
__device__ __align__(16) float2 g_D2 [(size_t)NN * DD];            // split deg*h
__device__ __align__(16) float2 g_A2 [(size_t)NN * DD];            // split agg
__device__ __align__(16) float2 g_W2 [(size_t)8 * 512 * 256];      // split weights
__device__ __align__(16) float  g_deg[NN];
__device__ __align__(16) float  g_pool[DD];
__device__ int g_cnt[NN];
__device__ int g_rowptr[NN + 1];
__device__ int g_pos[NN];
__device__ int g_esrc[EE];
__device__ int g_is64;

// ---------------- helpers ----------------
__device__ __forceinline__ uint32_t smem_u32(const void* p) {
    uint32_t a;
    asm("{ .reg .u64 t; cvta.to.shared.u64 t, %1; cvt.u32.u64 %0, t; }" : "=r"(a) : "l"(p));
    return a;
}
__device__ __forceinline__ uint32_t f2tf(float x) {
    uint32_t r;
    asm("cvt.rna.tf32.f32 %0, %1;" : "=r"(r) : "f"(x));
    return r;
}
__device__ __forceinline__ float2 split2(float x) {
    uint32_t hi = f2tf(x);
    uint32_t lo = f2tf(x - __uint_as_float(hi));
    return make_float2(__uint_as_float(hi), __uint_as_float(lo));
}
__device__ __forceinline__ void cp16(uint32_t dst, const void* src, bool pred) {
    int sz = pred ? 16 : 0;
    asm volatile("cp.async.cg.shared.global [%0], [%1], 16, %2;"
                 :: "r"(dst), "l"(src), "r"(sz) : "memory");
}
__device__ __forceinline__ void cp_commit() {
    asm volatile("cp.async.commit_group;" ::: "memory");
}
template <int N>
__device__ __forceinline__ void cp_wait() {
    asm volatile("cp.async.wait_group %0;" :: "n"(N) : "memory");
}
__device__ __forceinline__ void mma_tf32(float* c, const uint32_t* a, const uint32_t* b) {
    asm volatile(
        "mma.sync.aligned.m16n8k8.row.col.f32.tf32.tf32.f32 "
        "{%0,%1,%2,%3}, {%4,%5,%6,%7}, {%8,%9}, {%0,%1,%2,%3};"
        : "+f"(c[0]), "+f"(c[1]), "+f"(c[2]), "+f"(c[3])
        : "r"(a[0]), "r"(a[1]), "r"(a[2]), "r"(a[3]), "r"(b[0]), "r"(b[1]));
}
__device__ __forceinline__ int idx_at(const void* buf, int is64, size_t idx) {
    if (is64) return (int)((const long long*)buf)[idx];
    return ((const int*)buf)[idx];
}

// ---------------- dtype sniffer ----------------
__global__ void detect_kernel(const int* __restrict__ edges_w, int* __restrict__ is64) {
    __shared__ int nz;
    if (threadIdx.x == 0) nz = 0;
    __syncthreads();
    int any = 0;
    for (int t = threadIdx.x; t < 4096; t += blockDim.x)
        if (edges_w[2 * t + 1] != 0) any = 1;
    if (any) atomicAdd(&nz, 1);
    __syncthreads();
    if (threadIdx.x == 0) *is64 = (nz == 0) ? 1 : 0;
}

// ---------------- utility ----------------
__global__ void zero_i_kernel(int* __restrict__ p, int n) {
    int i = blockIdx.x * blockDim.x + threadIdx.x;
    if (i < n) p[i] = 0;
}
__global__ void zero_f_kernel(float* __restrict__ p, int n) {
    int i = blockIdx.x * blockDim.x + threadIdx.x;
    if (i < n) p[i] = 0.0f;
}

// ---------------- CSR build ----------------
__global__ void count_kernel(const void* __restrict__ edges, const int* __restrict__ is64p,
                             int* __restrict__ cnt) {
    int e = blockIdx.x * blockDim.x + threadIdx.x;
    if (e >= EE) return;
    int d = idx_at(edges, *is64p, (size_t)EE + e);
    if (d >= 0 && d < NN) atomicAdd(&cnt[d], 1);
}

__global__ void scan_kernel(const int* __restrict__ cnt, int* __restrict__ rowptr,
                            int* __restrict__ pos, float* __restrict__ deg) {
    __shared__ int part[SCAN_T];
    int t = threadIdx.x;
    const int CH = (NN + SCAN_T - 1) / SCAN_T;
    int base = t * CH;
    int s = 0;
#pragma unroll
    for (int i = 0; i < CH; ++i) {
        int idx = base + i;
        if (idx < NN) s += cnt[idx];
    }
    part[t] = s;
    __syncthreads();
    for (int off = 1; off < SCAN_T; off <<= 1) {
        int v = (t >= off) ? part[t - off] : 0;
        __syncthreads();
        part[t] += v;
        __syncthreads();
    }
    int prefix = (t == 0) ? 0 : part[t - 1];
#pragma unroll
    for (int i = 0; i < CH; ++i) {
        int idx = base + i;
        if (idx < NN) {
            rowptr[idx] = prefix;
            pos[idx] = prefix;
            int c = cnt[idx];
            deg[idx] = (float)c;
            prefix += c;
        }
    }
    if (t == SCAN_T - 1) rowptr[NN] = part[SCAN_T - 1];
}

__global__ void fill_kernel(const void* __restrict__ edges, const int* __restrict__ is64p,
                            int* __restrict__ pos, int* __restrict__ esrc) {
    int e = blockIdx.x * blockDim.x + threadIdx.x;
    if (e >= EE) return;
    int is64 = *is64p;
    int s = idx_at(edges, is64, (size_t)e);
    int d = idx_at(edges, is64, (size_t)EE + e);
    if (d < 0 || d >= NN) return;
    if (s < 0) s = 0; if (s >= NN) s = NN - 1;
    int slot = atomicAdd(&pos[d], 1);
    if (slot >= 0 && slot < EE) esrc[slot] = s;
}

// ---------------- split weights once ----------------
__global__ void split_w_kernel(const float* __restrict__ Wm, const float* __restrict__ Wu,
                               float2* __restrict__ W2) {
    size_t i = (size_t)blockIdx.x * 256 + threadIdx.x;
    if (i >= (size_t)8 * 512 * 256) return;
    size_t mat = i / (512 * 256);
    size_t off = i % (512 * 256);
    float v = (mat < 4) ? Wm[mat * 512 * 256 + off] : Wu[(mat - 4) * 512 * 256 + off];
    W2[i] = split2(v);
}

// ---------------- initial node states (plain + split) ----------------
__global__ void init_kernel(const float* __restrict__ nodes,
                            const void* __restrict__ types, const int* __restrict__ is64p,
                            const float* __restrict__ type_emb,
                            const float* __restrict__ W_proj,
                            const float* __restrict__ b_proj,
                            float* __restrict__ h, float2* __restrict__ hs) {
    int v = blockIdx.x;
    int j = threadIdx.x;
    __shared__ float sn[FEAT];
    if (j < FEAT) sn[j] = nodes[(size_t)v * FEAT + j];
    __syncthreads();
    int t = idx_at(types, *is64p, (size_t)v);
    if (t < 0) t = 0; if (t > 9) t = 9;
    float acc = b_proj[j] + type_emb[(size_t)t * DD + j];
#pragma unroll
    for (int k = 0; k < FEAT; ++k)
        acc += sn[k] * W_proj[(size_t)k * DD + j];
    h [(size_t)v * DD + j] = acc;
    hs[(size_t)v * DD + j] = split2(acc);
}

// ---------------- gather: S2 = split(sum h[src]); D2 = split(deg*h) ----------------
__global__ __launch_bounds__(DD)
void agg_gather_kernel(const int* __restrict__ rowptr,
                       const int* __restrict__ esrc,
                       const float* __restrict__ h,
                       float2* __restrict__ S2, float2* __restrict__ D2) {
    int v = blockIdx.x;
    int j = threadIdx.x;
    int beg = rowptr[v];
    int end = rowptr[v + 1];
    float acc = 0.0f;
    int i = beg;
    for (; i + 4 <= end; i += 4) {
        int s0 = esrc[i + 0];
        int s1 = esrc[i + 1];
        int s2 = esrc[i + 2];
        int s3 = esrc[i + 3];
        float a0 = h[(size_t)s0 * DD + j];
        float a1 = h[(size_t)s1 * DD + j];
        float a2 = h[(size_t)s2 * DD + j];
        float a3 = h[(size_t)s3 * DD + j];
        acc += (a0 + a1) + (a2 + a3);
    }
    for (; i < end; ++i)
        acc += h[(size_t)esrc[i] * DD + j];
    float degv = (float)(end - beg);
    float hv = h[(size_t)v * DD + j];
    S2[(size_t)v * DD + j] = split2(acc);
    D2[(size_t)v * DD + j] = split2(degv * hv);
}

// ---------------- 3xTF32 GEMM on pre-split operands ----------------
// out[r][c] = sum_k P[r][k]*W[k][c] + sum_k Q[r][k]*W[256+k][c]
//             + bias[c]*(bias_scaled ? deg[r] : 1),  optional relu.
// P2/Q2/W2 hold (hi, lo) tf32 splits. x*y ~= hi*hi + hi*lo + lo*hi.
#define RSA 36     // float2 row stride of A tile (36 mod 16 == 4 -> conflict-free)
#define RSB 132    // float2 row stride of B tile (132 mod 16 == 4)
#define A_BYTES (128 * RSA * 8)            // 36864
#define B_BYTES (32 * RSB * 8)             // 33792
#define STAGE_BYTES (A_BYTES + B_BYTES)    // 70656
#define GM_SMEM (2 * STAGE_BYTES)          // 141312

__global__ __launch_bounds__(256)
void mma_gemm2_kernel(const float2* __restrict__ P2, const float2* __restrict__ Q2,
                      const float2* __restrict__ W2, const float* __restrict__ bias,
                      const float* __restrict__ deg,
                      int bias_scaled, int do_relu,
                      float* __restrict__ out_plain, float2* __restrict__ out_split) {
    extern __shared__ char dyn[];
    uint32_t sb = smem_u32(dyn);

    int tid = threadIdx.x;
    int wid = tid >> 5;
    int lane = tid & 31;
    int tq = lane >> 2;
    int tr = lane & 3;
    int warp_m = wid & 1;
    int warp_n = wid >> 1;
    int rowBase = blockIdx.y * 128;
    int colBase = blockIdx.x * 128;

    int arow = tid >> 1;            // 0..127
    int ahalf = (tid & 1) * 16;     // 0 / 16 pairs
    int brow = tid >> 3;            // 0..31
    int bcol = (tid & 7) * 16;      // 0..112 pairs

    float acc[4][4][4];
#pragma unroll
    for (int mt = 0; mt < 4; ++mt)
#pragma unroll
        for (int nt = 0; nt < 4; ++nt)
#pragma unroll
            for (int q = 0; q < 4; ++q) acc[mt][nt][q] = 0.0f;

    int gr = rowBase + arow;
    bool arow_ok = gr < NN;
    const float2* asrc_base[2] = { P2 + (size_t)(arow_ok ? gr : 0) * DD + ahalf,
                                   Q2 + (size_t)(arow_ok ? gr : 0) * DD + ahalf };

    // tile loader (cp.async): ktile kt -> phase p = kt>>3, k0 = (kt&7)*32
#define LOAD_TILE(kt, st)                                                          \
    {                                                                              \
        int p_ = (kt) >> 3;                                                        \
        int k0_ = ((kt) & 7) * 32;                                                 \
        uint32_t adst = sb + (st) * STAGE_BYTES + (uint32_t)(arow * RSA + ahalf) * 8; \
        const float2* as_ = asrc_base[p_] + k0_;                                   \
        _Pragma("unroll")                                                          \
        for (int i_ = 0; i_ < 8; ++i_) cp16(adst + i_ * 16, as_ + i_ * 2, arow_ok); \
        uint32_t bdst = sb + (st) * STAGE_BYTES + A_BYTES + (uint32_t)(brow * RSB + bcol) * 8; \
        const float2* bs_ = W2 + (size_t)(p_ * 256 + k0_ + brow) * DD + colBase + bcol; \
        _Pragma("unroll")                                                          \
        for (int i_ = 0; i_ < 8; ++i_) cp16(bdst + i_ * 16, bs_ + i_ * 2, true);   \
    }

    LOAD_TILE(0, 0);
    cp_commit();

#pragma unroll 1
    for (int kt = 0; kt < 16; ++kt) {
        int st = kt & 1;
        if (kt + 1 < 16) {
            LOAD_TILE(kt + 1, (kt + 1) & 1);
            cp_commit();
            cp_wait<1>();
        } else {
            cp_wait<0>();
        }
        __syncthreads();

        const float2* As2 = (const float2*)(dyn + st * STAGE_BYTES);
        const float2* Bs2 = (const float2*)(dyn + st * STAGE_BYTES + A_BYTES);
#pragma unroll
        for (int kk = 0; kk < 32; kk += 8) {
            uint32_t ah[4][4], al[4][4], bh[4][2], bl[4][2];
#pragma unroll
            for (int mt = 0; mt < 4; ++mt) {
                int m0 = warp_m * 64 + mt * 16 + tq;
                const float2* ap = &As2[m0 * RSA + kk + tr];
                float2 f0 = ap[0];
                float2 f1 = ap[8 * RSA];
                float2 f2 = ap[4];
                float2 f3 = ap[8 * RSA + 4];
                ah[mt][0] = __float_as_uint(f0.x); al[mt][0] = __float_as_uint(f0.y);
                ah[mt][1] = __float_as_uint(f1.x); al[mt][1] = __float_as_uint(f1.y);
                ah[mt][2] = __float_as_uint(f2.x); al[mt][2] = __float_as_uint(f2.y);
                ah[mt][3] = __float_as_uint(f3.x); al[mt][3] = __float_as_uint(f3.y);
            }
#pragma unroll
            for (int nt = 0; nt < 4; ++nt) {
                int n0 = warp_n * 32 + nt * 8 + tq;
                const float2* bp = &Bs2[(kk + tr) * RSB + n0];
                float2 g0 = bp[0];
                float2 g1 = bp[4 * RSB];
                bh[nt][0] = __float_as_uint(g0.x); bl[nt][0] = __float_as_uint(g0.y);
                bh[nt][1] = __float_as_uint(g1.x); bl[nt][1] = __float_as_uint(g1.y);
            }
#pragma unroll
            for (int mt = 0; mt < 4; ++mt)
#pragma unroll
                for (int nt = 0; nt < 4; ++nt) {
                    mma_tf32(acc[mt][nt], ah[mt], bl[nt]);
                    mma_tf32(acc[mt][nt], al[mt], bh[nt]);
                    mma_tf32(acc[mt][nt], ah[mt], bh[nt]);
                }
        }
        __syncthreads();
    }

    // epilogue: write plain fp32 (optional) + split (for next GEMM)
#pragma unroll
    for (int mt = 0; mt < 4; ++mt) {
        int r0 = rowBase + warp_m * 64 + mt * 16 + tq;
        int r1 = r0 + 8;
        float bs0 = 1.0f, bs1 = 1.0f;
        if (bias_scaled) {
            if (r0 < NN) bs0 = deg[r0];
            if (r1 < NN) bs1 = deg[r1];
        }
#pragma unroll
        for (int nt = 0; nt < 4; ++nt) {
            int c = colBase + warp_n * 32 + nt * 8 + tr * 2;
            float b0 = bias[c], b1 = bias[c + 1];
#pragma unroll
            for (int half = 0; half < 2; ++half) {
                int r = half ? r1 : r0;
                float bsc = half ? bs1 : bs0;
                if (r >= NN) continue;
                float vx = acc[mt][nt][half * 2 + 0] + b0 * bsc;
                float vy = acc[mt][nt][half * 2 + 1] + b1 * bsc;
                if (do_relu) { vx = fmaxf(vx, 0.f); vy = fmaxf(vy, 0.f); }
                if (out_plain) {
                    float2 v; v.x = vx; v.y = vy;
                    *reinterpret_cast<float2*>(out_plain + (size_t)r * DD + c) = v;
                }
                float2 sx = split2(vx);
                float2 sy = split2(vy);
                float4 sv;
                sv.x = sx.x; sv.y = sx.y; sv.z = sy.x; sv.w = sy.y;
                *reinterpret_cast<float4*>(out_split + (size_t)r * DD + c) = sv;
            }
        }
    }
}

// ---------------- max pool over nodes ----------------
__global__ void pool_kernel(const float* __restrict__ h, float* __restrict__ pool) {
    int j = threadIdx.x;
    int r0 = blockIdx.x * 256;
    int r1 = min(r0 + 256, NN);
    float m = 0.0f;
    for (int r = r0; r < r1; ++r)
        m = fmaxf(m, h[(size_t)r * DD + j]);
    atomicMax(reinterpret_cast<int*>(&pool[j]), __float_as_int(m));
}

// ---------------- final projection ----------------
__global__ void out_kernel(const float* __restrict__ pool,
                           const float* __restrict__ W_out,
                           const float* __restrict__ b_out,
                           float* __restrict__ out) {
    __shared__ float sp[DD];
    int j = threadIdx.x;
    sp[j] = pool[j];
    __syncthreads();
    float acc = b_out[j];
#pragma unroll 8
    for (int k = 0; k < DD; ++k)
        acc += sp[k] * W_out[(size_t)k * DD + j];
    out[j] = acc;
}

// ---------------- launch ----------------
extern "C" void kernel_launch(void* const* d_in, const int* in_sizes, int n_in,
                              void* d_out, int out_size) {
    const float* nodes      = (const float*)d_in[0];
    const void*  edges      = d_in[1];
    const void*  node_types = d_in[2];
    const float* type_emb   = (const float*)d_in[3];
    const float* W_proj     = (const float*)d_in[4];
    const float* b_proj     = (const float*)d_in[5];
    const float* W_msg      = (const float*)d_in[6];
    const float* b_msg      = (const float*)d_in[7];
    const float* W_upd      = (const float*)d_in[8];
    const float* b_upd      = (const float*)d_in[9];
    const float* W_out      = (const float*)d_in[10];
    const float* b_out      = (const float*)d_in[11];
    float* out = (float*)d_out;

    float *h_p, *h2_p, *deg_p, *pool_p;
    float2 *hs0_p, *hs1_p, *S2_p, *D2_p, *A2_p, *W2_p;
    int *cnt_p, *rowptr_p, *pos_p, *esrc_p, *is64_p;
    cudaGetSymbolAddress((void**)&h_p,      g_h);
    cudaGetSymbolAddress((void**)&h2_p,     g_h2);
    cudaGetSymbolAddress((void**)&hs0_p,    g_hs0);
    cudaGetSymbolAddress((void**)&hs1_p,    g_hs1);
    cudaGetSymbolAddress((void**)&S2_p,     g_S2);
    cudaGetSymbolAddress((void**)&D2_p,     g_D2);
    cudaGetSymbolAddress((void**)&A2_p,     g_A2);
    cudaGetSymbolAddress((void**)&W2_p,     g_W2);
    cudaGetSymbolAddress((void**)&deg_p,    g_deg);
    cudaGetSymbolAddress((void**)&pool_p,   g_pool);
    cudaGetSymbolAddress((void**)&cnt_p,    g_cnt);
    cudaGetSymbolAddress((void**)&rowptr_p, g_rowptr);
    cudaGetSymbolAddress((void**)&pos_p,    g_pos);
    cudaGetSymbolAddress((void**)&esrc_p,   g_esrc);
    cudaGetSymbolAddress((void**)&is64_p,   g_is64);

    cudaFuncSetAttribute(mma_gemm2_kernel,
                         cudaFuncAttributeMaxDynamicSharedMemorySize, GM_SMEM);

    // sniff index dtype
    detect_kernel<<<1, 256>>>((const int*)edges, is64_p);

    // CSR build
    zero_i_kernel<<<(NN + 255) / 256, 256>>>(cnt_p, NN);
    count_kernel<<<(EE + 255) / 256, 256>>>(edges, is64_p, cnt_p);
    scan_kernel<<<1, SCAN_T>>>(cnt_p, rowptr_p, pos_p, deg_p);
    fill_kernel<<<(EE + 255) / 256, 256>>>(edges, is64_p, pos_p, esrc_p);

    // split weights
    split_w_kernel<<<(8 * 512 * 256 + 255) / 256, 256>>>(W_msg, W_upd, W2_p);

    // initial states (plain + split)
    init_kernel<<<NN, DD>>>(nodes, node_types, is64_p, type_emb, W_proj, b_proj,
                            h_p, hs0_p);

    float*  h_cur  = h_p;   float*  h_nxt  = h2_p;
    float2* hs_cur = hs0_p; float2* hs_nxt = hs1_p;
    dim3 ggrid(2, (NN + 127) / 128);

    for (int i = 0; i < HOPS; ++i) {
        agg_gather_kernel<<<NN, DD>>>(rowptr_p, esrc_p, h_cur, S2_p, D2_p);
        // agg = S@Wm_top + (deg*h)@Wm_bot + deg*b_msg  -> split only
        mma_gemm2_kernel<<<ggrid, 256, GM_SMEM>>>(S2_p, D2_p,
                                                  W2_p + (size_t)i * 131072,
                                                  b_msg + (size_t)i * DD,
                                                  deg_p, 1, 0,
                                                  nullptr, A2_p);
        // h_next = relu(h@Wu_top + agg@Wu_bot + b_upd) -> plain + split
        mma_gemm2_kernel<<<ggrid, 256, GM_SMEM>>>(hs_cur, A2_p,
                                                  W2_p + (size_t)(4 + i) * 131072,
                                                  b_upd + (size_t)i * DD,
                                                  nullptr, 0, 1,
                                                  h_nxt, hs_nxt);
        float*  t  = h_cur;  h_cur  = h_nxt;  h_nxt  = t;
        float2* t2 = hs_cur; hs_cur = hs_nxt; hs_nxt = t2;
    }

    // pool + output
    zero_f_kernel<<<1, DD>>>(pool_p, DD);
    pool_kernel<<<(NN + 255) / 256, DD>>>(h_cur, pool_p);
    out_kernel<<<1, DD>>>(pool_p, W_out, b_out, out);
}

// round 9
// speedup vs baseline: 1.6173x; 1.6173x over previous
#include <cuda_runtime.h>
#include <cuda_bf16.h>
#include <cstdint>

#define NN 25000
#define EE 400000
#define DD 256
#define FEAT 32
#define HOPS 4

// ---------------- device scratch (static, no allocation) ----------------
__device__ __align__(16) float g_h  [(size_t)NN * DD];
__device__ __align__(16) float g_h2 [(size_t)NN * DD];
__device__ __align__(16) float g_S  [(size_t)NN * DD];
__device__ __align__(16) float g_Wc [(size_t)HOPS * 512 * 256];  // composed weights
__device__ __align__(16) float g_bc [(size_t)HOPS * 256];        // composed bias
__device__ __align__(16) float g_deg[NN];
__device__ __align__(16) float g_pool[DD];
__device__ int g_cnt[NN];
__device__ int g_rowptr[NN + 1];
__device__ int g_pos[NN];
__device__ int g_esrc[EE];
__device__ int g_is64;

// ---------------- helpers ----------------
__device__ __forceinline__ int idx_at(const void* buf, int is64, size_t idx) {
    if (is64) return (int)((const long long*)buf)[idx];
    return ((const int*)buf)[idx];
}
__device__ __forceinline__ void mma_tf32(float* c, const uint32_t* a, const uint32_t* b) {
    asm volatile(
        "mma.sync.aligned.m16n8k8.row.col.f32.tf32.tf32.f32 "
        "{%0,%1,%2,%3}, {%4,%5,%6,%7}, {%8,%9}, {%0,%1,%2,%3};"
        : "+f"(c[0]), "+f"(c[1]), "+f"(c[2]), "+f"(c[3])
        : "r"(a[0]), "r"(a[1]), "r"(a[2]), "r"(a[3]), "r"(b[0]), "r"(b[1]));
}
__device__ __forceinline__ uint32_t f2tf(float x) {
    uint32_t r;
    asm("cvt.rna.tf32.f32 %0, %1;" : "=r"(r) : "f"(x));
    return r;
}
__device__ __forceinline__ void split_tf(float x, uint32_t& hi, uint32_t& lo) {
    hi = f2tf(x);
    lo = f2tf(x - __uint_as_float(hi));
}

// ---------------- dtype sniffer ----------------
__global__ void detect_kernel(const int* __restrict__ edges_w, int* __restrict__ is64) {
    __shared__ int nz;
    if (threadIdx.x == 0) nz = 0;
    __syncthreads();
    int any = 0;
    for (int t = threadIdx.x; t < 4096; t += blockDim.x)
        if (edges_w[2 * t + 1] != 0) any = 1;
    if (any) atomicAdd(&nz, 1);
    __syncthreads();
    if (threadIdx.x == 0) *is64 = (nz == 0) ? 1 : 0;
}

// ---------------- utility ----------------
__global__ void zero_i_kernel(int* __restrict__ p, int n) {
    int i = blockIdx.x * blockDim.x + threadIdx.x;
    if (i < n) p[i] = 0;
}
__global__ void zero_f_kernel(float* __restrict__ p, int n) {
    int i = blockIdx.x * blockDim.x + threadIdx.x;
    if (i < n) p[i] = 0.0f;
}

// ---------------- CSR build ----------------
__global__ void count_kernel(const void* __restrict__ edges, const int* __restrict__ is64p,
                             int* __restrict__ cnt) {
    int e = blockIdx.x * blockDim.x + threadIdx.x;
    if (e >= EE) return;
    int d = idx_at(edges, *is64p, (size_t)EE + e);
    if (d >= 0 && d < NN) atomicAdd(&cnt[d], 1);
}

// single-block scan (shfl-based) over NN counts
__global__ void scan_kernel(const int* __restrict__ cnt, int* __restrict__ rowptr,
                            int* __restrict__ pos, float* __restrict__ deg) {
    const int T = 1024;
    const int CH = (NN + T - 1) / T;   // 25
    int t = threadIdx.x;
    int lane = t & 31;
    int w = t >> 5;
    int base = t * CH;
    int s = 0;
#pragma unroll
    for (int i = 0; i < CH; ++i) {
        int idx = base + i;
        if (idx < NN) s += cnt[idx];
    }
    // warp inclusive scan
    int v = s;
#pragma unroll
    for (int o = 1; o < 32; o <<= 1) {
        int u = __shfl_up_sync(0xFFFFFFFFu, v, o);
        if (lane >= o) v += u;
    }
    __shared__ int wsum[32];
    if (lane == 31) wsum[w] = v;
    __syncthreads();
    if (w == 0) {
        int x = wsum[lane];
#pragma unroll
        for (int o = 1; o < 32; o <<= 1) {
            int u = __shfl_up_sync(0xFFFFFFFFu, x, o);
            if (lane >= o) x += u;
        }
        wsum[lane] = x;
    }
    __syncthreads();
    int prefix = (v - s) + (w > 0 ? wsum[w - 1] : 0);
#pragma unroll
    for (int i = 0; i < CH; ++i) {
        int idx = base + i;
        if (idx < NN) {
            rowptr[idx] = prefix;
            pos[idx] = prefix;
            int c = cnt[idx];
            deg[idx] = (float)c;
            prefix += c;
        }
    }
    if (t == T - 1) rowptr[NN] = wsum[31];
}

__global__ void fill_kernel(const void* __restrict__ edges, const int* __restrict__ is64p,
                            int* __restrict__ pos, int* __restrict__ esrc) {
    int e = blockIdx.x * blockDim.x + threadIdx.x;
    if (e >= EE) return;
    int is64 = *is64p;
    int s = idx_at(edges, is64, (size_t)e);
    int d = idx_at(edges, is64, (size_t)EE + e);
    if (d < 0 || d >= NN) return;
    if (s < 0) s = 0; if (s >= NN) s = NN - 1;
    int slot = atomicAdd(&pos[d], 1);
    if (slot >= 0 && slot < EE) esrc[slot] = s;
}

// ---------------- weight composition ----------------
// Wc[i][k][c] = sum_j Wm[i][k][j] * Wu[i][256+j][c],  k in [0,512)
// (k<256 -> Wm_top@Wu_bot; k>=256 -> Wm_bot@Wu_bot)
__global__ void compose_kernel(const float* __restrict__ Wm, const float* __restrict__ Wu,
                               float* __restrict__ Wc) {
    int i = blockIdx.x >> 7;           // hop
    int k4 = (blockIdx.x & 127) * 4;   // 4 k-rows per block
    int c = threadIdx.x;
    __shared__ float row[4][256];
#pragma unroll
    for (int q = 0; q < 4; ++q)
        row[q][c] = Wm[((size_t)i * 512 + k4 + q) * 256 + c];
    __syncthreads();
    const float* wub = Wu + ((size_t)i * 512 + 256) * 256;
    float acc0 = 0.f, acc1 = 0.f, acc2 = 0.f, acc3 = 0.f;
#pragma unroll 8
    for (int j = 0; j < 256; ++j) {
        float wv = wub[(size_t)j * 256 + c];
        acc0 += row[0][j] * wv;
        acc1 += row[1][j] * wv;
        acc2 += row[2][j] * wv;
        acc3 += row[3][j] * wv;
    }
    Wc[((size_t)i * 512 + k4 + 0) * 256 + c] = acc0;
    Wc[((size_t)i * 512 + k4 + 1) * 256 + c] = acc1;
    Wc[((size_t)i * 512 + k4 + 2) * 256 + c] = acc2;
    Wc[((size_t)i * 512 + k4 + 3) * 256 + c] = acc3;
}

// bc[i][c] = sum_j b_msg[i][j] * Wu[i][256+j][c]
__global__ void compose_bias_kernel(const float* __restrict__ b_msg,
                                    const float* __restrict__ Wu,
                                    float* __restrict__ bc) {
    int i = blockIdx.x;
    int c = threadIdx.x;
    __shared__ float bm[256];
    bm[c] = b_msg[(size_t)i * 256 + c];
    __syncthreads();
    const float* wub = Wu + ((size_t)i * 512 + 256) * 256;
    float acc = 0.f;
#pragma unroll 8
    for (int j = 0; j < 256; ++j)
        acc += bm[j] * wub[(size_t)j * 256 + c];
    bc[(size_t)i * 256 + c] = acc;
}

// ---------------- initial node states ----------------
__global__ void init_kernel(const float* __restrict__ nodes,
                            const void* __restrict__ types, const int* __restrict__ is64p,
                            const float* __restrict__ type_emb,
                            const float* __restrict__ W_proj,
                            const float* __restrict__ b_proj,
                            float* __restrict__ h) {
    int v = blockIdx.x;
    int j = threadIdx.x;
    __shared__ float sn[FEAT];
    if (j < FEAT) sn[j] = nodes[(size_t)v * FEAT + j];
    __syncthreads();
    int t = idx_at(types, *is64p, (size_t)v);
    if (t < 0) t = 0; if (t > 9) t = 9;
    float acc = b_proj[j] + type_emb[(size_t)t * DD + j];
#pragma unroll
    for (int k = 0; k < FEAT; ++k)
        acc += sn[k] * W_proj[(size_t)k * DD + j];
    h[(size_t)v * DD + j] = acc;
}

// ---------------- per-dst gather: S[v] = sum over incoming edges of h[src] ----
__global__ __launch_bounds__(DD)
void agg_gather_kernel(const int* __restrict__ rowptr,
                       const int* __restrict__ esrc,
                       const float* __restrict__ h,
                       float* __restrict__ S) {
    int v = blockIdx.x;
    int j = threadIdx.x;
    int beg = rowptr[v];
    int end = rowptr[v + 1];
    float acc = 0.0f;
    int i = beg;
    for (; i + 4 <= end; i += 4) {
        int s0 = esrc[i + 0];
        int s1 = esrc[i + 1];
        int s2 = esrc[i + 2];
        int s3 = esrc[i + 3];
        float a0 = h[(size_t)s0 * DD + j];
        float a1 = h[(size_t)s1 * DD + j];
        float a2 = h[(size_t)s2 * DD + j];
        float a3 = h[(size_t)s3 * DD + j];
        acc += (a0 + a1) + (a2 + a3);
    }
    for (; i < end; ++i)
        acc += h[(size_t)esrc[i] * DD + j];
    S[(size_t)v * DD + j] = acc;
}

// ---------------- hybrid fused hop GEMM ----------------
// h'[r][c] = relu( sum_k h[r][k]*Wu[k][c] + sum_k S[r][k]*Wc1[k][c]
//                + deg[r]*sum_k h[r][k]*Wc2[k][c] + b_upd[c] + deg[r]*bc[c] )
// Per-CTA path: ~44% of CTAs use 3xTF32 HMMA (tensor pipe), rest fp32 FFMA.
#define APAD 36
#define BPAD 136
// smem union: HMMA needs 128*36 + 32*136 = 8960 floats; FFMA needs 2048.
__global__ __launch_bounds__(256, 2)
void hybrid_gemm_kernel(const float* __restrict__ h, const float* __restrict__ S,
                        const float* __restrict__ Wu,   // [512][256] rows 0..255 used
                        const float* __restrict__ Wc,   // [512][256] composed
                        const float* __restrict__ b_upd_i,
                        const float* __restrict__ bc_i,
                        const float* __restrict__ deg,
                        float* __restrict__ out) {
    __shared__ __align__(16) float sm[8960];
    int tid = threadIdx.x;
    int rowBase = blockIdx.y * 128;
    int colBase = blockIdx.x * 128;
    int lin = blockIdx.y * 2 + blockIdx.x;
    bool useH = (lin % 9) < 4;

    const float* Xs[3] = { h, S, h };
    const float* Bp[3] = { Wu, Wc, Wc + 65536 };

    if (useH) {
        // ======== 3xTF32 HMMA path (round-7 proven body, 3 phases) ========
        float* Am = sm;            // [128][APAD]
        float* Bm = sm + 4608;     // [32][BPAD]
        int wid = tid >> 5, lane = tid & 31;
        int tq = lane >> 2, tr = lane & 3;
        int warp_m = wid & 1, warp_n = wid >> 1;

        float acc[4][4][4];
#pragma unroll
        for (int mt = 0; mt < 4; ++mt)
#pragma unroll
            for (int nt = 0; nt < 4; ++nt)
#pragma unroll
                for (int q = 0; q < 4; ++q) acc[mt][nt][q] = 0.0f;

        int arow = tid >> 1, ahalf = (tid & 1) * 16;
        int brow = tid >> 3, bcol = (tid & 7) * 16;
        int gr = rowBase + arow;
        bool ok = gr < NN;
        float rs = ok ? deg[gr] : 0.f;

#pragma unroll 1
        for (int p = 0; p < 3; ++p) {
            const float* X = Xs[p];
            const float* B = Bp[p];
            bool scaled = (p == 2);
#pragma unroll 1
            for (int kt = 0; kt < 8; ++kt) {
                int k0 = kt * 32;
                __syncthreads();
                {
                    float4 v[4];
                    if (ok) {
                        const float4* src = reinterpret_cast<const float4*>(
                            X + (size_t)gr * DD + k0 + ahalf);
#pragma unroll
                        for (int i = 0; i < 4; ++i) v[i] = src[i];
                        if (scaled) {
#pragma unroll
                            for (int i = 0; i < 4; ++i) {
                                v[i].x *= rs; v[i].y *= rs; v[i].z *= rs; v[i].w *= rs;
                            }
                        }
                    } else {
#pragma unroll
                        for (int i = 0; i < 4; ++i) v[i] = make_float4(0.f, 0.f, 0.f, 0.f);
                    }
#pragma unroll
                    for (int i = 0; i < 4; ++i)
                        *reinterpret_cast<float4*>(&Am[arow * APAD + ahalf + i * 4]) = v[i];
                }
                {
                    const float4* src = reinterpret_cast<const float4*>(
                        B + (size_t)(k0 + brow) * DD + colBase + bcol);
#pragma unroll
                    for (int i = 0; i < 4; ++i)
                        *reinterpret_cast<float4*>(&Bm[brow * BPAD + bcol + i * 4]) = src[i];
                }
                __syncthreads();
#pragma unroll
                for (int kk = 0; kk < 32; kk += 8) {
                    uint32_t ah[4][4], al[4][4], bh[4][2], bl[4][2];
#pragma unroll
                    for (int mt = 0; mt < 4; ++mt) {
                        int m0 = warp_m * 64 + mt * 16 + tq;
                        const float* ap = &Am[m0 * APAD + kk + tr];
                        split_tf(ap[0],            ah[mt][0], al[mt][0]);
                        split_tf(ap[8 * APAD],     ah[mt][1], al[mt][1]);
                        split_tf(ap[4],            ah[mt][2], al[mt][2]);
                        split_tf(ap[8 * APAD + 4], ah[mt][3], al[mt][3]);
                    }
#pragma unroll
                    for (int nt = 0; nt < 4; ++nt) {
                        int n0 = warp_n * 32 + nt * 8 + tq;
                        const float* bp = &Bm[(kk + tr) * BPAD + n0];
                        split_tf(bp[0],        bh[nt][0], bl[nt][0]);
                        split_tf(bp[4 * BPAD], bh[nt][1], bl[nt][1]);
                    }
#pragma unroll
                    for (int mt = 0; mt < 4; ++mt)
#pragma unroll
                        for (int nt = 0; nt < 4; ++nt) {
                            mma_tf32(acc[mt][nt], ah[mt], bl[nt]);
                            mma_tf32(acc[mt][nt], al[mt], bh[nt]);
                            mma_tf32(acc[mt][nt], ah[mt], bh[nt]);
                        }
                }
            }
        }
        // epilogue
#pragma unroll
        for (int mt = 0; mt < 4; ++mt) {
            int r0 = rowBase + warp_m * 64 + mt * 16 + tq;
            int r1 = r0 + 8;
            float d0 = (r0 < NN) ? deg[r0] : 0.f;
            float d1 = (r1 < NN) ? deg[r1] : 0.f;
#pragma unroll
            for (int nt = 0; nt < 4; ++nt) {
                int c = colBase + warp_n * 32 + nt * 8 + tr * 2;
                float bu0 = b_upd_i[c], bu1 = b_upd_i[c + 1];
                float bb0 = bc_i[c],   bb1 = bc_i[c + 1];
                if (r0 < NN) {
                    float2 v;
                    v.x = fmaxf(acc[mt][nt][0] + bu0 + d0 * bb0, 0.f);
                    v.y = fmaxf(acc[mt][nt][1] + bu1 + d0 * bb1, 0.f);
                    *reinterpret_cast<float2*>(out + (size_t)r0 * DD + c) = v;
                }
                if (r1 < NN) {
                    float2 v;
                    v.x = fmaxf(acc[mt][nt][2] + bu0 + d1 * bb0, 0.f);
                    v.y = fmaxf(acc[mt][nt][3] + bu1 + d1 * bb1, 0.f);
                    *reinterpret_cast<float2*>(out + (size_t)r1 * DD + c) = v;
                }
            }
        }
    } else {
        // ======== fp32 FFMA path (round-4 proven body, 3 phases) ========
        float* Af = sm;            // [8][128]
        float* Bf = sm + 1024;     // [8][128]
        int tx = tid & 15, ty = tid >> 4;

        float acc[8][8];
#pragma unroll
        for (int i = 0; i < 8; ++i)
#pragma unroll
            for (int j = 0; j < 8; ++j) acc[i][j] = 0.0f;

        int la_row = tid >> 1, la_k = (tid & 1) * 4;
        int lb_k = tid >> 5, lb_col = (tid & 31) * 4;
        int gr = rowBase + la_row;
        bool ok = gr < NN;
        float rs = ok ? deg[gr] : 0.f;

#pragma unroll 1
        for (int p = 0; p < 3; ++p) {
            const float* X = Xs[p];
            const float* B = Bp[p];
            bool scaled = (p == 2);
#pragma unroll 1
            for (int k0 = 0; k0 < DD; k0 += 8) {
                float4 av = make_float4(0.f, 0.f, 0.f, 0.f);
                if (ok) {
                    av = *reinterpret_cast<const float4*>(X + (size_t)gr * DD + k0 + la_k);
                    if (scaled) { av.x *= rs; av.y *= rs; av.z *= rs; av.w *= rs; }
                }
                float4 bv = *reinterpret_cast<const float4*>(
                    B + (size_t)(k0 + lb_k) * DD + colBase + lb_col);
                Af[(la_k + 0) * 128 + la_row] = av.x;
                Af[(la_k + 1) * 128 + la_row] = av.y;
                Af[(la_k + 2) * 128 + la_row] = av.z;
                Af[(la_k + 3) * 128 + la_row] = av.w;
                *reinterpret_cast<float4*>(&Bf[lb_k * 128 + lb_col]) = bv;
                __syncthreads();
#pragma unroll
                for (int k = 0; k < 8; ++k) {
                    float a[8], b[8];
                    *reinterpret_cast<float4*>(&a[0]) =
                        *reinterpret_cast<const float4*>(&Af[k * 128 + ty * 4]);
                    *reinterpret_cast<float4*>(&a[4]) =
                        *reinterpret_cast<const float4*>(&Af[k * 128 + 64 + ty * 4]);
                    *reinterpret_cast<float4*>(&b[0]) =
                        *reinterpret_cast<const float4*>(&Bf[k * 128 + tx * 4]);
                    *reinterpret_cast<float4*>(&b[4]) =
                        *reinterpret_cast<const float4*>(&Bf[k * 128 + 64 + tx * 4]);
#pragma unroll
                    for (int i = 0; i < 8; ++i)
#pragma unroll
                        for (int j = 0; j < 8; ++j)
                            acc[i][j] += a[i] * b[j];
                }
                __syncthreads();
            }
        }
        // epilogue
#pragma unroll
        for (int i = 0; i < 8; ++i) {
            int rloc = (i < 4) ? (ty * 4 + i) : (64 + ty * 4 + i - 4);
            int r = rowBase + rloc;
            if (r >= NN) continue;
            float dr = deg[r];
#pragma unroll
            for (int j = 0; j < 8; ++j) {
                int c = colBase + ((j < 4) ? (tx * 4 + j) : (64 + tx * 4 + j - 4));
                float v = acc[i][j] + b_upd_i[c] + dr * bc_i[c];
                out[(size_t)r * DD + c] = fmaxf(v, 0.f);
            }
        }
    }
}

// ---------------- max pool over nodes ----------------
__global__ void pool_kernel(const float* __restrict__ h, float* __restrict__ pool) {
    int j = threadIdx.x;
    int r0 = blockIdx.x * 256;
    int r1 = min(r0 + 256, NN);
    float m = 0.0f;
    for (int r = r0; r < r1; ++r)
        m = fmaxf(m, h[(size_t)r * DD + j]);
    atomicMax(reinterpret_cast<int*>(&pool[j]), __float_as_int(m));
}

// ---------------- final projection ----------------
__global__ void out_kernel(const float* __restrict__ pool,
                           const float* __restrict__ W_out,
                           const float* __restrict__ b_out,
                           float* __restrict__ out) {
    __shared__ float sp[DD];
    int j = threadIdx.x;
    sp[j] = pool[j];
    __syncthreads();
    float acc = b_out[j];
#pragma unroll 8
    for (int k = 0; k < DD; ++k)
        acc += sp[k] * W_out[(size_t)k * DD + j];
    out[j] = acc;
}

// ---------------- launch ----------------
extern "C" void kernel_launch(void* const* d_in, const int* in_sizes, int n_in,
                              void* d_out, int out_size) {
    const float* nodes      = (const float*)d_in[0];
    const void*  edges      = d_in[1];
    const void*  node_types = d_in[2];
    const float* type_emb   = (const float*)d_in[3];
    const float* W_proj     = (const float*)d_in[4];
    const float* b_proj     = (const float*)d_in[5];
    const float* W_msg      = (const float*)d_in[6];   // [4][512][256]
    const float* b_msg      = (const float*)d_in[7];
    const float* W_upd      = (const float*)d_in[8];   // [4][512][256]
    const float* b_upd      = (const float*)d_in[9];
    const float* W_out      = (const float*)d_in[10];
    const float* b_out      = (const float*)d_in[11];
    float* out = (float*)d_out;

    float *h_p, *h2_p, *S_p, *Wc_p, *bc_p, *deg_p, *pool_p;
    int *cnt_p, *rowptr_p, *pos_p, *esrc_p, *is64_p;
    cudaGetSymbolAddress((void**)&h_p,      g_h);
    cudaGetSymbolAddress((void**)&h2_p,     g_h2);
    cudaGetSymbolAddress((void**)&S_p,      g_S);
    cudaGetSymbolAddress((void**)&Wc_p,     g_Wc);
    cudaGetSymbolAddress((void**)&bc_p,     g_bc);
    cudaGetSymbolAddress((void**)&deg_p,    g_deg);
    cudaGetSymbolAddress((void**)&pool_p,   g_pool);
    cudaGetSymbolAddress((void**)&cnt_p,    g_cnt);
    cudaGetSymbolAddress((void**)&rowptr_p, g_rowptr);
    cudaGetSymbolAddress((void**)&pos_p,    g_pos);
    cudaGetSymbolAddress((void**)&esrc_p,   g_esrc);
    cudaGetSymbolAddress((void**)&is64_p,   g_is64);

    // sniff index dtype
    detect_kernel<<<1, 256>>>((const int*)edges, is64_p);

    // CSR build
    zero_i_kernel<<<(NN + 255) / 256, 256>>>(cnt_p, NN);
    count_kernel<<<(EE + 255) / 256, 256>>>(edges, is64_p, cnt_p);
    scan_kernel<<<1, 1024>>>(cnt_p, rowptr_p, pos_p, deg_p);
    fill_kernel<<<(EE + 255) / 256, 256>>>(edges, is64_p, pos_p, esrc_p);

    // composed weights + bias
    compose_kernel<<<HOPS * 128, 256>>>(W_msg, W_upd, Wc_p);
    compose_bias_kernel<<<HOPS, 256>>>(b_msg, W_upd, bc_p);

    // initial states
    init_kernel<<<NN, DD>>>(nodes, node_types, is64_p, type_emb, W_proj, b_proj, h_p);

    float* h_cur = h_p;
    float* h_nxt = h2_p;
    dim3 ggrid(2, (NN + 127) / 128);

    for (int i = 0; i < HOPS; ++i) {
        agg_gather_kernel<<<NN, DD>>>(rowptr_p, esrc_p, h_cur, S_p);
        hybrid_gemm_kernel<<<ggrid, 256>>>(h_cur, S_p,
                                           W_upd + (size_t)i * 512 * 256,
                                           Wc_p  + (size_t)i * 512 * 256,
                                           b_upd + (size_t)i * DD,
                                           bc_p  + (size_t)i * DD,
                                           deg_p, h_nxt);
        float* t = h_cur; h_cur = h_nxt; h_nxt = t;
    }

    // pool + output
    zero_f_kernel<<<1, DD>>>(pool_p, DD);
    pool_kernel<<<(NN + 255) / 256, DD>>>(h_cur, pool_p);
    out_kernel<<<1, DD>>>(pool_p, W_out, b_out, out);
}

// round 10
// speedup vs baseline: 1.7946x; 1.1096x over previous
#include <cuda_runtime.h>
#include <cuda_bf16.h>
#include <cstdint>

#define NN 25000
#define EE 400000
#define DD 256
#define FEAT 32
#define HOPS 4

// ---------------- device scratch (static, no allocation) ----------------
__device__ __align__(16) float g_h  [(size_t)NN * DD];
__device__ __align__(16) float g_h2 [(size_t)NN * DD];
__device__ __align__(16) float g_S  [(size_t)NN * DD];
__device__ __align__(16) float g_Wc [(size_t)HOPS * 512 * 256];
__device__ __align__(16) float g_bc [(size_t)HOPS * 256];
__device__ __align__(16) float g_deg[NN];
__device__ __align__(16) float g_pool[DD];
__device__ int g_cnt[NN];
__device__ int g_rowptr[NN + 1];
__device__ int g_pos[NN];
__device__ int g_esrc[EE];
__device__ int g_is64;

// ---------------- helpers ----------------
__device__ __forceinline__ int idx_at(const void* buf, int is64, size_t idx) {
    if (is64) return (int)((const long long*)buf)[idx];
    return ((const int*)buf)[idx];
}
__device__ __forceinline__ void mma_bf16(float* c, const uint32_t* a, const uint32_t* b) {
    asm volatile(
        "mma.sync.aligned.m16n8k16.row.col.f32.bf16.bf16.f32 "
        "{%0,%1,%2,%3}, {%4,%5,%6,%7}, {%8,%9}, {%0,%1,%2,%3};"
        : "+f"(c[0]), "+f"(c[1]), "+f"(c[2]), "+f"(c[3])
        : "r"(a[0]), "r"(a[1]), "r"(a[2]), "r"(a[3]), "r"(b[0]), "r"(b[1]));
}
// pack two floats as bf16x2 (low half = first arg), return residuals
__device__ __forceinline__ uint32_t bf16pack(float a, float b) {
    __nv_bfloat162 h;
    h.x = __float2bfloat16_rn(a);
    h.y = __float2bfloat16_rn(b);
    return *reinterpret_cast<uint32_t*>(&h);
}

// ---------------- dtype sniffer ----------------
__global__ void detect_kernel(const int* __restrict__ edges_w, int* __restrict__ is64) {
    __shared__ int nz;
    if (threadIdx.x == 0) nz = 0;
    __syncthreads();
    int any = 0;
    for (int t = threadIdx.x; t < 4096; t += blockDim.x)
        if (edges_w[2 * t + 1] != 0) any = 1;
    if (any) atomicAdd(&nz, 1);
    __syncthreads();
    if (threadIdx.x == 0) *is64 = (nz == 0) ? 1 : 0;
}

// ---------------- utility ----------------
__global__ void zero_i_kernel(int* __restrict__ p, int n) {
    int i = blockIdx.x * blockDim.x + threadIdx.x;
    if (i < n) p[i] = 0;
}
__global__ void zero_f_kernel(float* __restrict__ p, int n) {
    int i = blockIdx.x * blockDim.x + threadIdx.x;
    if (i < n) p[i] = 0.0f;
}

// ---------------- CSR build ----------------
__global__ void count_kernel(const void* __restrict__ edges, const int* __restrict__ is64p,
                             int* __restrict__ cnt) {
    int e = blockIdx.x * blockDim.x + threadIdx.x;
    if (e >= EE) return;
    int d = idx_at(edges, *is64p, (size_t)EE + e);
    if (d >= 0 && d < NN) atomicAdd(&cnt[d], 1);
}

__global__ void scan_kernel(const int* __restrict__ cnt, int* __restrict__ rowptr,
                            int* __restrict__ pos, float* __restrict__ deg) {
    const int T = 1024;
    const int CH = (NN + T - 1) / T;
    int t = threadIdx.x;
    int lane = t & 31;
    int w = t >> 5;
    int base = t * CH;
    int s = 0;
#pragma unroll
    for (int i = 0; i < CH; ++i) {
        int idx = base + i;
        if (idx < NN) s += cnt[idx];
    }
    int v = s;
#pragma unroll
    for (int o = 1; o < 32; o <<= 1) {
        int u = __shfl_up_sync(0xFFFFFFFFu, v, o);
        if (lane >= o) v += u;
    }
    __shared__ int wsum[32];
    if (lane == 31) wsum[w] = v;
    __syncthreads();
    if (w == 0) {
        int x = wsum[lane];
#pragma unroll
        for (int o = 1; o < 32; o <<= 1) {
            int u = __shfl_up_sync(0xFFFFFFFFu, x, o);
            if (lane >= o) x += u;
        }
        wsum[lane] = x;
    }
    __syncthreads();
    int prefix = (v - s) + (w > 0 ? wsum[w - 1] : 0);
#pragma unroll
    for (int i = 0; i < CH; ++i) {
        int idx = base + i;
        if (idx < NN) {
            rowptr[idx] = prefix;
            pos[idx] = prefix;
            int c = cnt[idx];
            deg[idx] = (float)c;
            prefix += c;
        }
    }
    if (t == T - 1) rowptr[NN] = wsum[31];
}

__global__ void fill_kernel(const void* __restrict__ edges, const int* __restrict__ is64p,
                            int* __restrict__ pos, int* __restrict__ esrc) {
    int e = blockIdx.x * blockDim.x + threadIdx.x;
    if (e >= EE) return;
    int is64 = *is64p;
    int s = idx_at(edges, is64, (size_t)e);
    int d = idx_at(edges, is64, (size_t)EE + e);
    if (d < 0 || d >= NN) return;
    if (s < 0) s = 0; if (s >= NN) s = NN - 1;
    int slot = atomicAdd(&pos[d], 1);
    if (slot >= 0 && slot < EE) esrc[slot] = s;
}

// ---------------- weight composition ----------------
__global__ void compose_kernel(const float* __restrict__ Wm, const float* __restrict__ Wu,
                               float* __restrict__ Wc) {
    int i = blockIdx.x >> 7;
    int k4 = (blockIdx.x & 127) * 4;
    int c = threadIdx.x;
    __shared__ float row[4][256];
#pragma unroll
    for (int q = 0; q < 4; ++q)
        row[q][c] = Wm[((size_t)i * 512 + k4 + q) * 256 + c];
    __syncthreads();
    const float* wub = Wu + ((size_t)i * 512 + 256) * 256;
    float acc0 = 0.f, acc1 = 0.f, acc2 = 0.f, acc3 = 0.f;
#pragma unroll 8
    for (int j = 0; j < 256; ++j) {
        float wv = wub[(size_t)j * 256 + c];
        acc0 += row[0][j] * wv;
        acc1 += row[1][j] * wv;
        acc2 += row[2][j] * wv;
        acc3 += row[3][j] * wv;
    }
    Wc[((size_t)i * 512 + k4 + 0) * 256 + c] = acc0;
    Wc[((size_t)i * 512 + k4 + 1) * 256 + c] = acc1;
    Wc[((size_t)i * 512 + k4 + 2) * 256 + c] = acc2;
    Wc[((size_t)i * 512 + k4 + 3) * 256 + c] = acc3;
}

__global__ void compose_bias_kernel(const float* __restrict__ b_msg,
                                    const float* __restrict__ Wu,
                                    float* __restrict__ bc) {
    int i = blockIdx.x;
    int c = threadIdx.x;
    __shared__ float bm[256];
    bm[c] = b_msg[(size_t)i * 256 + c];
    __syncthreads();
    const float* wub = Wu + ((size_t)i * 512 + 256) * 256;
    float acc = 0.f;
#pragma unroll 8
    for (int j = 0; j < 256; ++j)
        acc += bm[j] * wub[(size_t)j * 256 + c];
    bc[(size_t)i * 256 + c] = acc;
}

// ---------------- initial node states ----------------
__global__ void init_kernel(const float* __restrict__ nodes,
                            const void* __restrict__ types, const int* __restrict__ is64p,
                            const float* __restrict__ type_emb,
                            const float* __restrict__ W_proj,
                            const float* __restrict__ b_proj,
                            float* __restrict__ h) {
    int v = blockIdx.x;
    int j = threadIdx.x;
    __shared__ float sn[FEAT];
    if (j < FEAT) sn[j] = nodes[(size_t)v * FEAT + j];
    __syncthreads();
    int t = idx_at(types, *is64p, (size_t)v);
    if (t < 0) t = 0; if (t > 9) t = 9;
    float acc = b_proj[j] + type_emb[(size_t)t * DD + j];
#pragma unroll
    for (int k = 0; k < FEAT; ++k)
        acc += sn[k] * W_proj[(size_t)k * DD + j];
    h[(size_t)v * DD + j] = acc;
}

// ---------------- per-dst gather (float4-vectorized, 4 nodes/block) ----------------
__global__ __launch_bounds__(256)
void agg_gather_kernel(const int* __restrict__ rowptr,
                       const int* __restrict__ esrc,
                       const float* __restrict__ h,
                       float* __restrict__ S) {
    int v = blockIdx.x * 4 + (threadIdx.x >> 6);
    int tx = (threadIdx.x & 63) * 4;       // feature offset
    if (v >= NN) return;
    int beg = rowptr[v];
    int end = rowptr[v + 1];
    float4 acc = make_float4(0.f, 0.f, 0.f, 0.f);
    int i = beg;
    for (; i + 4 <= end; i += 4) {
        int s0 = esrc[i + 0];
        int s1 = esrc[i + 1];
        int s2 = esrc[i + 2];
        int s3 = esrc[i + 3];
        float4 a0 = *reinterpret_cast<const float4*>(h + (size_t)s0 * DD + tx);
        float4 a1 = *reinterpret_cast<const float4*>(h + (size_t)s1 * DD + tx);
        float4 a2 = *reinterpret_cast<const float4*>(h + (size_t)s2 * DD + tx);
        float4 a3 = *reinterpret_cast<const float4*>(h + (size_t)s3 * DD + tx);
        acc.x += (a0.x + a1.x) + (a2.x + a3.x);
        acc.y += (a0.y + a1.y) + (a2.y + a3.y);
        acc.z += (a0.z + a1.z) + (a2.z + a3.z);
        acc.w += (a0.w + a1.w) + (a2.w + a3.w);
    }
    for (; i < end; ++i) {
        float4 a = *reinterpret_cast<const float4*>(h + (size_t)esrc[i] * DD + tx);
        acc.x += a.x; acc.y += a.y; acc.z += a.z; acc.w += a.w;
    }
    *reinterpret_cast<float4*>(S + (size_t)v * DD + tx) = acc;
}

// ---------------- hybrid fused hop GEMM ----------------
// h'[r][c] = relu( h@Wu_top + S@Wc1 + deg*(h@Wc2) + b_upd + deg*bc )
// H path (60% CTAs): 2-split bf16 m16n8k16 HMMA; F path: fp32 FFMA.
// bf16 smem: row stride 40 bf16 (= 20 words) -> conflict-free frag LDS.
#define HST 40                 // bf16 elements per row
#define A_HI 0
#define A_LO 10240
#define B_HI 20480
#define B_LO 30720
#define SMU_BYTES 40960

__global__ __launch_bounds__(256, 2)
void hybrid_gemm_kernel(const float* __restrict__ h, const float* __restrict__ S,
                        const float* __restrict__ Wu,
                        const float* __restrict__ Wc,
                        const float* __restrict__ b_upd_i,
                        const float* __restrict__ bc_i,
                        const float* __restrict__ deg,
                        float* __restrict__ out) {
    __shared__ __align__(16) uint8_t smu[SMU_BYTES];
    int tid = threadIdx.x;
    int rowBase = blockIdx.y * 128;
    int colBase = blockIdx.x * 128;
    int lin = blockIdx.y * 2 + blockIdx.x;
    bool useH = (lin % 5) < 3;     // 60% tensor path

    const float* Xs[3] = { h, S, h };
    const float* Bp[3] = { Wu, Wc, Wc + 65536 };

    if (useH) {
        // ======== 2-split bf16 HMMA path ========
        uint32_t* AhiW = (uint32_t*)(smu + A_HI);
        uint32_t* AloW = (uint32_t*)(smu + A_LO);
        uint32_t* BhiW = (uint32_t*)(smu + B_HI);
        uint32_t* BloW = (uint32_t*)(smu + B_LO);
        __nv_bfloat16* BhiH = (__nv_bfloat16*)(smu + B_HI);
        __nv_bfloat16* BloH = (__nv_bfloat16*)(smu + B_LO);

        int wid = tid >> 5, lane = tid & 31;
        int tq = lane >> 2, tr = lane & 3;
        int warp_m = wid & 1, warp_n = wid >> 1;

        float acc[4][4][4];
#pragma unroll
        for (int mt = 0; mt < 4; ++mt)
#pragma unroll
            for (int nt = 0; nt < 4; ++nt)
#pragma unroll
                for (int q = 0; q < 4; ++q) acc[mt][nt][q] = 0.0f;

        int arow = tid >> 1, ahalf = (tid & 1) * 16;
        int brow = tid >> 3, bcol = (tid & 7) * 16;
        int gr = rowBase + arow;
        bool ok = gr < NN;
        float rs = ok ? deg[gr] : 0.f;

#pragma unroll 1
        for (int p = 0; p < 3; ++p) {
            const float* X = Xs[p];
            const float* B = Bp[p];
            bool scaled = (p == 2);
#pragma unroll 1
            for (int kt = 0; kt < 8; ++kt) {
                int k0 = kt * 32;
                __syncthreads();
                // --- A tile [128][32] -> split bf16 hi/lo ---
                {
                    float4 v[4];
                    if (ok) {
                        const float4* src = reinterpret_cast<const float4*>(
                            X + (size_t)gr * DD + k0 + ahalf);
#pragma unroll
                        for (int i = 0; i < 4; ++i) v[i] = src[i];
                        if (scaled) {
#pragma unroll
                            for (int i = 0; i < 4; ++i) {
                                v[i].x *= rs; v[i].y *= rs; v[i].z *= rs; v[i].w *= rs;
                            }
                        }
                    } else {
#pragma unroll
                        for (int i = 0; i < 4; ++i) v[i] = make_float4(0.f, 0.f, 0.f, 0.f);
                    }
#pragma unroll
                    for (int i = 0; i < 4; ++i) {
                        int w0 = arow * (HST / 2) + (ahalf >> 1) + i * 2;
                        uint32_t h0 = bf16pack(v[i].x, v[i].y);
                        uint32_t h1 = bf16pack(v[i].z, v[i].w);
                        __nv_bfloat162 hb0 = *reinterpret_cast<__nv_bfloat162*>(&h0);
                        __nv_bfloat162 hb1 = *reinterpret_cast<__nv_bfloat162*>(&h1);
                        uint32_t l0 = bf16pack(v[i].x - __bfloat162float(hb0.x),
                                               v[i].y - __bfloat162float(hb0.y));
                        uint32_t l1 = bf16pack(v[i].z - __bfloat162float(hb1.x),
                                               v[i].w - __bfloat162float(hb1.y));
                        AhiW[w0] = h0; AhiW[w0 + 1] = h1;
                        AloW[w0] = l0; AloW[w0 + 1] = l1;
                    }
                }
                // --- B tile [32 k][128 n] -> transposed split bf16 [n][k] ---
                {
                    const float4* src = reinterpret_cast<const float4*>(
                        B + (size_t)(k0 + brow) * DD + colBase + bcol);
#pragma unroll
                    for (int i = 0; i < 4; ++i) {
                        float4 w = src[i];
                        int n = bcol + i * 4;
                        float e[4] = { w.x, w.y, w.z, w.w };
#pragma unroll
                        for (int j = 0; j < 4; ++j) {
                            __nv_bfloat16 hb = __float2bfloat16_rn(e[j]);
                            BhiH[(n + j) * HST + brow] = hb;
                            BloH[(n + j) * HST + brow] =
                                __float2bfloat16_rn(e[j] - __bfloat162float(hb));
                        }
                    }
                }
                __syncthreads();
                // --- compute: 2 k16 steps ---
#pragma unroll
                for (int ks = 0; ks < 2; ++ks) {
                    int kw = ks * 8;
                    uint32_t ah[4][4], al[4][4], bh[4][2], bl[4][2];
#pragma unroll
                    for (int mt = 0; mt < 4; ++mt) {
                        int m0 = warp_m * 64 + mt * 16 + tq;
                        int base = m0 * (HST / 2) + kw + tr;
                        ah[mt][0] = AhiW[base];
                        ah[mt][1] = AhiW[base + 8 * (HST / 2)];
                        ah[mt][2] = AhiW[base + 4];
                        ah[mt][3] = AhiW[base + 8 * (HST / 2) + 4];
                        al[mt][0] = AloW[base];
                        al[mt][1] = AloW[base + 8 * (HST / 2)];
                        al[mt][2] = AloW[base + 4];
                        al[mt][3] = AloW[base + 8 * (HST / 2) + 4];
                    }
#pragma unroll
                    for (int nt = 0; nt < 4; ++nt) {
                        int n0 = warp_n * 32 + nt * 8 + tq;
                        int base = n0 * (HST / 2) + kw + tr;
                        bh[nt][0] = BhiW[base];
                        bh[nt][1] = BhiW[base + 4];
                        bl[nt][0] = BloW[base];
                        bl[nt][1] = BloW[base + 4];
                    }
#pragma unroll
                    for (int mt = 0; mt < 4; ++mt)
#pragma unroll
                        for (int nt = 0; nt < 4; ++nt) {
                            mma_bf16(acc[mt][nt], ah[mt], bl[nt]);
                            mma_bf16(acc[mt][nt], al[mt], bh[nt]);
                            mma_bf16(acc[mt][nt], ah[mt], bh[nt]);
                        }
                }
            }
        }
        // epilogue
#pragma unroll
        for (int mt = 0; mt < 4; ++mt) {
            int r0 = rowBase + warp_m * 64 + mt * 16 + tq;
            int r1 = r0 + 8;
            float d0 = (r0 < NN) ? deg[r0] : 0.f;
            float d1 = (r1 < NN) ? deg[r1] : 0.f;
#pragma unroll
            for (int nt = 0; nt < 4; ++nt) {
                int c = colBase + warp_n * 32 + nt * 8 + tr * 2;
                float bu0 = b_upd_i[c], bu1 = b_upd_i[c + 1];
                float bb0 = bc_i[c],   bb1 = bc_i[c + 1];
                if (r0 < NN) {
                    float2 v;
                    v.x = fmaxf(acc[mt][nt][0] + bu0 + d0 * bb0, 0.f);
                    v.y = fmaxf(acc[mt][nt][1] + bu1 + d0 * bb1, 0.f);
                    *reinterpret_cast<float2*>(out + (size_t)r0 * DD + c) = v;
                }
                if (r1 < NN) {
                    float2 v;
                    v.x = fmaxf(acc[mt][nt][2] + bu0 + d1 * bb0, 0.f);
                    v.y = fmaxf(acc[mt][nt][3] + bu1 + d1 * bb1, 0.f);
                    *reinterpret_cast<float2*>(out + (size_t)r1 * DD + c) = v;
                }
            }
        }
    } else {
        // ======== fp32 FFMA path ========
        float* Af = (float*)smu;            // [8][128]
        float* Bf = (float*)(smu + 4096);   // [8][128]
        int tx = tid & 15, ty = tid >> 4;

        float acc[8][8];
#pragma unroll
        for (int i = 0; i < 8; ++i)
#pragma unroll
            for (int j = 0; j < 8; ++j) acc[i][j] = 0.0f;

        int la_row = tid >> 1, la_k = (tid & 1) * 4;
        int lb_k = tid >> 5, lb_col = (tid & 31) * 4;
        int gr = rowBase + la_row;
        bool ok = gr < NN;
        float rs = ok ? deg[gr] : 0.f;

#pragma unroll 1
        for (int p = 0; p < 3; ++p) {
            const float* X = Xs[p];
            const float* B = Bp[p];
            bool scaled = (p == 2);
#pragma unroll 1
            for (int k0 = 0; k0 < DD; k0 += 8) {
                float4 av = make_float4(0.f, 0.f, 0.f, 0.f);
                if (ok) {
                    av = *reinterpret_cast<const float4*>(X + (size_t)gr * DD + k0 + la_k);
                    if (scaled) { av.x *= rs; av.y *= rs; av.z *= rs; av.w *= rs; }
                }
                float4 bv = *reinterpret_cast<const float4*>(
                    B + (size_t)(k0 + lb_k) * DD + colBase + lb_col);
                Af[(la_k + 0) * 128 + la_row] = av.x;
                Af[(la_k + 1) * 128 + la_row] = av.y;
                Af[(la_k + 2) * 128 + la_row] = av.z;
                Af[(la_k + 3) * 128 + la_row] = av.w;
                *reinterpret_cast<float4*>(&Bf[lb_k * 128 + lb_col]) = bv;
                __syncthreads();
#pragma unroll
                for (int k = 0; k < 8; ++k) {
                    float a[8], b[8];
                    *reinterpret_cast<float4*>(&a[0]) =
                        *reinterpret_cast<const float4*>(&Af[k * 128 + ty * 4]);
                    *reinterpret_cast<float4*>(&a[4]) =
                        *reinterpret_cast<const float4*>(&Af[k * 128 + 64 + ty * 4]);
                    *reinterpret_cast<float4*>(&b[0]) =
                        *reinterpret_cast<const float4*>(&Bf[k * 128 + tx * 4]);
                    *reinterpret_cast<float4*>(&b[4]) =
                        *reinterpret_cast<const float4*>(&Bf[k * 128 + 64 + tx * 4]);
#pragma unroll
                    for (int i = 0; i < 8; ++i)
#pragma unroll
                        for (int j = 0; j < 8; ++j)
                            acc[i][j] += a[i] * b[j];
                }
                __syncthreads();
            }
        }
#pragma unroll
        for (int i = 0; i < 8; ++i) {
            int rloc = (i < 4) ? (ty * 4 + i) : (64 + ty * 4 + i - 4);
            int r = rowBase + rloc;
            if (r >= NN) continue;
            float dr = deg[r];
#pragma unroll
            for (int j = 0; j < 8; ++j) {
                int c = colBase + ((j < 4) ? (tx * 4 + j) : (64 + tx * 4 + j - 4));
                float v = acc[i][j] + b_upd_i[c] + dr * bc_i[c];
                out[(size_t)r * DD + c] = fmaxf(v, 0.f);
            }
        }
    }
}

// ---------------- max pool over nodes ----------------
__global__ void pool_kernel(const float* __restrict__ h, float* __restrict__ pool) {
    int j = threadIdx.x;
    int r0 = blockIdx.x * 256;
    int r1 = min(r0 + 256, NN);
    float m = 0.0f;
    for (int r = r0; r < r1; ++r)
        m = fmaxf(m, h[(size_t)r * DD + j]);
    atomicMax(reinterpret_cast<int*>(&pool[j]), __float_as_int(m));
}

// ---------------- final projection ----------------
__global__ void out_kernel(const float* __restrict__ pool,
                           const float* __restrict__ W_out,
                           const float* __restrict__ b_out,
                           float* __restrict__ out) {
    __shared__ float sp[DD];
    int j = threadIdx.x;
    sp[j] = pool[j];
    __syncthreads();
    float acc = b_out[j];
#pragma unroll 8
    for (int k = 0; k < DD; ++k)
        acc += sp[k] * W_out[(size_t)k * DD + j];
    out[j] = acc;
}

// ---------------- launch ----------------
extern "C" void kernel_launch(void* const* d_in, const int* in_sizes, int n_in,
                              void* d_out, int out_size) {
    const float* nodes      = (const float*)d_in[0];
    const void*  edges      = d_in[1];
    const void*  node_types = d_in[2];
    const float* type_emb   = (const float*)d_in[3];
    const float* W_proj     = (const float*)d_in[4];
    const float* b_proj     = (const float*)d_in[5];
    const float* W_msg      = (const float*)d_in[6];
    const float* b_msg      = (const float*)d_in[7];
    const float* W_upd      = (const float*)d_in[8];
    const float* b_upd      = (const float*)d_in[9];
    const float* W_out      = (const float*)d_in[10];
    const float* b_out      = (const float*)d_in[11];
    float* out = (float*)d_out;

    float *h_p, *h2_p, *S_p, *Wc_p, *bc_p, *deg_p, *pool_p;
    int *cnt_p, *rowptr_p, *pos_p, *esrc_p, *is64_p;
    cudaGetSymbolAddress((void**)&h_p,      g_h);
    cudaGetSymbolAddress((void**)&h2_p,     g_h2);
    cudaGetSymbolAddress((void**)&S_p,      g_S);
    cudaGetSymbolAddress((void**)&Wc_p,     g_Wc);
    cudaGetSymbolAddress((void**)&bc_p,     g_bc);
    cudaGetSymbolAddress((void**)&deg_p,    g_deg);
    cudaGetSymbolAddress((void**)&pool_p,   g_pool);
    cudaGetSymbolAddress((void**)&cnt_p,    g_cnt);
    cudaGetSymbolAddress((void**)&rowptr_p, g_rowptr);
    cudaGetSymbolAddress((void**)&pos_p,    g_pos);
    cudaGetSymbolAddress((void**)&esrc_p,   g_esrc);
    cudaGetSymbolAddress((void**)&is64_p,   g_is64);

    // sniff index dtype
    detect_kernel<<<1, 256>>>((const int*)edges, is64_p);

    // CSR build
    zero_i_kernel<<<(NN + 255) / 256, 256>>>(cnt_p, NN);
    count_kernel<<<(EE + 255) / 256, 256>>>(edges, is64_p, cnt_p);
    scan_kernel<<<1, 1024>>>(cnt_p, rowptr_p, pos_p, deg_p);
    fill_kernel<<<(EE + 255) / 256, 256>>>(edges, is64_p, pos_p, esrc_p);

    // composed weights + bias
    compose_kernel<<<HOPS * 128, 256>>>(W_msg, W_upd, Wc_p);
    compose_bias_kernel<<<HOPS, 256>>>(b_msg, W_upd, bc_p);

    // initial states
    init_kernel<<<NN, DD>>>(nodes, node_types, is64_p, type_emb, W_proj, b_proj, h_p);

    float* h_cur = h_p;
    float* h_nxt = h2_p;
    dim3 ggrid(2, (NN + 127) / 128);

    for (int i = 0; i < HOPS; ++i) {
        agg_gather_kernel<<<(NN + 3) / 4, 256>>>(rowptr_p, esrc_p, h_cur, S_p);
        hybrid_gemm_kernel<<<ggrid, 256>>>(h_cur, S_p,
                                           W_upd + (size_t)i * 512 * 256,
                                           Wc_p  + (size_t)i * 512 * 256,
                                           b_upd + (size_t)i * DD,
                                           bc_p  + (size_t)i * DD,
                                           deg_p, h_nxt);
        float* t = h_cur; h_cur = h_nxt; h_nxt = t;
    }

    // pool + output
    zero_f_kernel<<<1, DD>>>(pool_p, DD);
    pool_kernel<<<(NN + 255) / 256, DD>>>(h_cur, pool_p);
    out_kernel<<<1, DD>>>(pool_p, W_out, b_out, out);
}